// round 3
// baseline (speedup 1.0000x reference)
#include <cuda_runtime.h>
#include <math.h>
#include <stdint.h>

#define HID   1024
#define GATES 4096
#define BB    8
#define TT    256
#define MM    2048          // B*T rows
#define VOC   50257

typedef unsigned long long u64;

// ---------------- scratch (device globals; no allocs allowed) ----------------
__device__ float g_emb[(size_t)MM * HID];            // [m=t*8+b][h]
__device__ float g_xproj[(size_t)MM * GATES];        // [m=t*8+b][4H]
__device__ float g_hall[(size_t)MM * HID];           // [m=b*256+t][h]  (decoder A)
__device__ float g_hbuf[2][BB * HID];
__device__ float g_c[BB * HID];
__device__ float g_lse[MM];
__device__ int   g_bar_cnt = 0;
__device__ int   g_bar_gen = 0;

// ---------------- helpers ----------------
__device__ __forceinline__ u64 fma2(u64 a, u64 b, u64 c) {
    u64 d;
    asm("fma.rn.f32x2 %0, %1, %2, %3;" : "=l"(d) : "l"(a), "l"(b), "l"(c));
    return d;
}
__device__ __forceinline__ u64 pk2(float lo, float hi) {
    u64 r; asm("mov.b64 %0, {%1, %2};" : "=l"(r) : "f"(lo), "f"(hi)); return r;
}
__device__ __forceinline__ float2 upk2(u64 v) {
    float2 r; asm("mov.b64 {%0, %1}, %2;" : "=f"(r.x), "=f"(r.y) : "l"(v)); return r;
}

__device__ __forceinline__ float fexp(float x) {
    float y = fmaxf(x * 1.4426950408889634f, -120.f);
    float n = rintf(y);
    float f = y - n;
    float p = 0.0013333558f;
    p = fmaf(p, f, 0.0096181291f);
    p = fmaf(p, f, 0.0555041087f);
    p = fmaf(p, f, 0.2402265069f);
    p = fmaf(p, f, 0.6931471806f);
    p = fmaf(p, f, 1.0f);
    return p * __int_as_float(((int)n + 127) << 23);
}

__device__ __forceinline__ void cpasync16(uint32_t dst, const void* src) {
    asm volatile("cp.async.cg.shared.global [%0], [%1], 16;\n" :: "r"(dst), "l"(src));
}

// ---------------- init ----------------
__global__ void zero_state_kernel() {
    int i = blockIdx.x * blockDim.x + threadIdx.x;
    if (i < BB * HID) { g_hbuf[0][i] = 0.f; g_c[i] = 0.f; }
}

// ---------------- embedding gather ----------------
__global__ void gather_kernel(const int* __restrict__ x, const float* __restrict__ embW) {
    int m = blockIdx.x;                 // m = t*8+b
    int t = m >> 3, b = m & 7;
    int tok = x[b * TT + t];
    const float4* src = (const float4*)(embW + (size_t)tok * HID);
    float4* dst = (float4*)(g_emb + (size_t)m * HID);
    dst[threadIdx.x] = src[threadIdx.x];
}

// ---------------- generic NT GEMM (f32x2 inner) ----------------
__global__ void __launch_bounds__(256)
gemm_nt_kernel(const float* __restrict__ A, const float* __restrict__ Bw,
               const float* __restrict__ bias1, const float* __restrict__ bias2,
               float* __restrict__ C, int M, int N, int K)
{
    __shared__ float As[16][132];
    __shared__ float Bs[16][68];
    int tid = threadIdx.x;
    int tx = tid & 15, ty = tid >> 4;
    int rowBase = blockIdx.y * 128;
    int colBase = blockIdx.x * 64;
    int aRow = tid >> 2;
    int aC4  = (tid & 3) * 4;

    u64 acc2[4][4];                    // [row-pair][col]
    #pragma unroll
    for (int i = 0; i < 4; i++)
        #pragma unroll
        for (int j = 0; j < 4; j++) acc2[i][j] = 0ull;

    for (int k0 = 0; k0 < K; k0 += 16) {
        #pragma unroll
        for (int rr = 0; rr < 2; rr++) {
            int r = aRow + rr * 64;
            float4 v = *(const float4*)(A + (size_t)(rowBase + r) * K + k0 + aC4);
            As[aC4 + 0][r] = v.x; As[aC4 + 1][r] = v.y;
            As[aC4 + 2][r] = v.z; As[aC4 + 3][r] = v.w;
        }
        {
            int n = colBase + aRow;
            float4 v = make_float4(0.f, 0.f, 0.f, 0.f);
            if (n < N) v = *(const float4*)(Bw + (size_t)n * K + k0 + aC4);
            Bs[aC4 + 0][aRow] = v.x; Bs[aC4 + 1][aRow] = v.y;
            Bs[aC4 + 2][aRow] = v.z; Bs[aC4 + 3][aRow] = v.w;
        }
        __syncthreads();
        #pragma unroll
        for (int kk = 0; kk < 16; kk++) {
            const u64* ap = (const u64*)&As[kk][ty * 8];   // 4 row-pairs
            u64 a0 = ap[0], a1 = ap[1], a2 = ap[2], a3 = ap[3];
            float4 b0 = *(const float4*)&Bs[kk][tx * 4];
            u64 bb0 = pk2(b0.x, b0.x), bb1 = pk2(b0.y, b0.y);
            u64 bb2 = pk2(b0.z, b0.z), bb3 = pk2(b0.w, b0.w);
            acc2[0][0] = fma2(a0, bb0, acc2[0][0]);
            acc2[0][1] = fma2(a0, bb1, acc2[0][1]);
            acc2[0][2] = fma2(a0, bb2, acc2[0][2]);
            acc2[0][3] = fma2(a0, bb3, acc2[0][3]);
            acc2[1][0] = fma2(a1, bb0, acc2[1][0]);
            acc2[1][1] = fma2(a1, bb1, acc2[1][1]);
            acc2[1][2] = fma2(a1, bb2, acc2[1][2]);
            acc2[1][3] = fma2(a1, bb3, acc2[1][3]);
            acc2[2][0] = fma2(a2, bb0, acc2[2][0]);
            acc2[2][1] = fma2(a2, bb1, acc2[2][1]);
            acc2[2][2] = fma2(a2, bb2, acc2[2][2]);
            acc2[2][3] = fma2(a2, bb3, acc2[2][3]);
            acc2[3][0] = fma2(a3, bb0, acc2[3][0]);
            acc2[3][1] = fma2(a3, bb1, acc2[3][1]);
            acc2[3][2] = fma2(a3, bb2, acc2[3][2]);
            acc2[3][3] = fma2(a3, bb3, acc2[3][3]);
        }
        __syncthreads();
    }

    #pragma unroll
    for (int j = 0; j < 4; j++) {
        int col = colBase + tx * 4 + j;
        if (col >= N) continue;
        float bv = 0.f;
        if (bias1) bv += bias1[col];
        if (bias2) bv += bias2[col];
        #pragma unroll
        for (int ip = 0; ip < 4; ip++) {
            float2 v = upk2(acc2[ip][j]);
            int row = rowBase + ty * 8 + ip * 2;
            C[(size_t)row * N + col]       = v.x + bv;
            C[(size_t)(row + 1) * N + col] = v.y + bv;
        }
    }
}

// ---------------- persistent LSTM: all 256 steps in one launch ----------------
// 128 CTAs (1/SM, forced by 226KB smem), CTA owns 8 hidden units (32 gate rows).
// w block staged in smem ONCE; per step: stage h (32KB) from global (L2, __ldcg),
// f32x2 dot products, smem k-reduce, epilogue by 64 threads (c in registers),
// software grid barrier between steps.
#define LS_SMEM_FLOATS (32*1024 + 8*1024 + 256*65 + 256)

__global__ void __launch_bounds__(256)
lstm_persistent_kernel(const float* __restrict__ w_hh)
{
    extern __shared__ float sm[];
    float* sm_w     = sm;
    float* sm_h     = sm + 32 * 1024;
    float* sm_part  = sm_h + 8 * 1024;
    float* sm_gates = sm_part + 256 * 65;

    int tid = threadIdx.x;
    int jb = blockIdx.x * 8;

    // ---- one-time: stage w block (32 rows x 1024) into smem ----
    {
        uint32_t sw = (uint32_t)__cvta_generic_to_shared(sm_w);
        #pragma unroll
        for (int i = 0; i < 32; i++) {
            int m = tid + 256 * i;            // 0..8191 float4
            int row = m >> 8;                 // 0..31 (g*8+jl)
            int c = m & 255;
            int g = row >> 3, jl = row & 7;
            const float4* src = (const float4*)w_hh + (size_t)(g * HID + jb + jl) * 256 + c;
            cpasync16(sw + (uint32_t)m * 16, src);
        }
        asm volatile("cp.async.commit_group;\n");
        asm volatile("cp.async.wait_group 0;\n" ::: "memory");
        __syncthreads();
    }

    int wid = tid >> 5, lane = tid & 31;
    int rg = wid & 3;                         // row-group (8 rows)
    int ks = (wid >> 2) * 32 + lane;          // k-slice 0..63 (float4 granularity)

    // epilogue thread state
    int ejl = tid >> 3, eb = tid & 7;         // valid for tid<64
    float c_reg = 0.f;

    for (int t = 0; t < TT; t++) {
        const float* hprev = g_hbuf[t & 1];
        float* hnext = g_hbuf[(t + 1) & 1];

        // ---- stage h (bypass L1: cross-CTA producer/consumer) ----
        {
            const float4* hp4 = (const float4*)hprev;
            float4* hs4 = (float4*)sm_h;
            #pragma unroll
            for (int i = 0; i < 8; i++) {
                int f = tid + 256 * i;
                hs4[f] = __ldcg(hp4 + f);
            }
        }
        __syncthreads();

        // ---- f32x2 dot products ----
        u64 acc[8][8];
        #pragma unroll
        for (int r = 0; r < 8; r++)
            #pragma unroll
            for (int b = 0; b < 8; b++) acc[r][b] = 0ull;

        const ulonglong2* w2 = (const ulonglong2*)sm_w;
        const ulonglong2* h2 = (const ulonglong2*)sm_h;
        #pragma unroll
        for (int q = 0; q < 4; q++) {
            int kb = q * 64 + ks;
            ulonglong2 hv[8];
            #pragma unroll
            for (int b = 0; b < 8; b++) hv[b] = h2[b * 256 + kb];
            #pragma unroll
            for (int r = 0; r < 8; r++) {
                ulonglong2 wv = w2[(rg * 8 + r) * 256 + kb];
                #pragma unroll
                for (int b = 0; b < 8; b++) {
                    acc[r][b] = fma2(wv.x, hv[b].x, acc[r][b]);
                    acc[r][b] = fma2(wv.y, hv[b].y, acc[r][b]);
                }
            }
        }

        // ---- k reduction via padded smem partials ----
        #pragma unroll
        for (int r = 0; r < 8; r++)
            #pragma unroll
            for (int b = 0; b < 8; b++) {
                float2 v = upk2(acc[r][b]);
                sm_part[((rg * 8 + r) * 8 + b) * 65 + ks] = v.x + v.y;
            }
        __syncthreads();

        {   // thread tid owns gate-row (tid>>3), batch (tid&7)
            float s0 = 0.f, s1 = 0.f, s2 = 0.f, s3 = 0.f;
            const float* p = sm_part + tid * 65;
            #pragma unroll
            for (int i = 0; i < 64; i += 4) {
                s0 += p[i]; s1 += p[i + 1]; s2 += p[i + 2]; s3 += p[i + 3];
            }
            int row = tid >> 3, b = tid & 7;
            int g = row >> 3, jl = row & 7;
            sm_gates[tid] = (s0 + s1) + (s2 + s3)
                          + g_xproj[((size_t)t * BB + b) * GATES + g * HID + jb + jl];
        }
        __syncthreads();

        if (tid < 64) {
            int j = jb + ejl;
            float gi = sm_gates[(0 * 8 + ejl) * 8 + eb];
            float gf = sm_gates[(1 * 8 + ejl) * 8 + eb];
            float gg = sm_gates[(2 * 8 + ejl) * 8 + eb];
            float go = sm_gates[(3 * 8 + ejl) * 8 + eb];
            gi = 1.f / (1.f + expf(-gi));
            gf = 1.f / (1.f + expf(-gf));
            gg = tanhf(gg);
            go = 1.f / (1.f + expf(-go));
            c_reg = gf * c_reg + gi * gg;
            float h = go * tanhf(c_reg);
            hnext[eb * HID + j] = h;
            g_hall[((size_t)eb * TT + t) * HID + j] = h;
            if (t == TT - 1) g_c[eb * HID + j] = c_reg;
            __threadfence();                 // publish h before arriving
        }

        // ---- software grid barrier ----
        __syncthreads();
        if (tid == 0) {
            int gen = *((volatile int*)&g_bar_gen);
            __threadfence();
            if (atomicAdd(&g_bar_cnt, 1) == (int)gridDim.x - 1) {
                g_bar_cnt = 0;
                __threadfence();
                atomicAdd(&g_bar_gen, 1);
            } else {
                while (*((volatile int*)&g_bar_gen) == gen) { }
            }
            __threadfence();
        }
        __syncthreads();
    }
}

// ---------------- per-row online logsumexp over VOC ----------------
__global__ void __launch_bounds__(256)
row_lse_kernel(const float* __restrict__ logits)
{
    int row = blockIdx.x;
    const float* p = logits + (size_t)row * VOC;
    float m = -1e30f, s = 0.f;
    for (int i = threadIdx.x; i < VOC; i += 256) {
        float v = p[i];
        if (v > m) { s = s * fexp(m - v) + 1.f; m = v; }
        else       { s += fexp(v - m); }
    }
    __shared__ float sm[256], ss[256];
    sm[threadIdx.x] = m; ss[threadIdx.x] = s;
    __syncthreads();
    for (int off = 128; off; off >>= 1) {
        if (threadIdx.x < off) {
            float m1 = sm[threadIdx.x], s1 = ss[threadIdx.x];
            float m2 = sm[threadIdx.x + off], s2 = ss[threadIdx.x + off];
            float mm = fmaxf(m1, m2);
            sm[threadIdx.x] = mm;
            ss[threadIdx.x] = s1 * fexp(m1 - mm) + s2 * fexp(m2 - mm);
        }
        __syncthreads();
    }
    if (threadIdx.x == 0) g_lse[row] = sm[0] + logf(ss[0]);
}

__global__ void __launch_bounds__(256)
sub_lse_kernel(float* __restrict__ out)
{
    int row = blockIdx.x;
    float l = g_lse[row];
    float* p = out + (size_t)row * VOC;
    for (int i = threadIdx.x; i < VOC; i += 256) p[i] -= l;
}

__global__ void write_hidden_kernel(float* __restrict__ out)
{
    int i = blockIdx.x * blockDim.x + threadIdx.x;
    size_t base = (size_t)MM * VOC;
    if (i < BB * HID)               out[base + i] = g_hbuf[0][i];
    else if (i < 2 * BB * HID)      out[base + i] = g_c[i - BB * HID];
}

// ---------------- launcher ----------------
extern "C" void kernel_launch(void* const* d_in, const int* in_sizes, int n_in,
                              void* d_out, int out_size)
{
    const int*   x     = (const int*)  d_in[0];
    const float* emb_W = (const float*)d_in[1];
    const float* w_ih  = (const float*)d_in[2];
    const float* w_hh  = (const float*)d_in[3];
    const float* b_ih  = (const float*)d_in[4];
    const float* b_hh  = (const float*)d_in[5];
    const float* dec_b = (const float*)d_in[6];
    float* out = (float*)d_out;

    float* emb_p;   cudaGetSymbolAddress((void**)&emb_p,   g_emb);
    float* xproj_p; cudaGetSymbolAddress((void**)&xproj_p, g_xproj);
    float* hall_p;  cudaGetSymbolAddress((void**)&hall_p,  g_hall);

    const int ls_smem = LS_SMEM_FLOATS * 4;   // 231424 bytes -> 1 CTA/SM
    cudaFuncSetAttribute(lstm_persistent_kernel,
                         cudaFuncAttributeMaxDynamicSharedMemorySize, ls_smem);

    // 1) reset recurrent state
    zero_state_kernel<<<(BB * HID + 255) / 256, 256>>>();

    // 2) embedding gather
    gather_kernel<<<MM, 256>>>(x, emb_W);

    // 3) x_proj = emb @ w_ih^T + (b_ih + b_hh)
    {
        dim3 grid(GATES / 64, MM / 128);
        gemm_nt_kernel<<<grid, 256>>>(emb_p, w_ih, b_ih, b_hh, xproj_p, MM, GATES, HID);
    }

    // 4) all 256 LSTM steps in ONE persistent launch (128 CTAs, all co-resident)
    lstm_persistent_kernel<<<HID / 8, 256, ls_smem>>>(w_hh);

    // 5) decoder: logits = h_all @ emb_W^T + dec_b
    {
        dim3 grid((VOC + 63) / 64, MM / 128);
        gemm_nt_kernel<<<grid, 256>>>(hall_p, emb_W, dec_b, (const float*)0, out, MM, VOC, HID);
    }

    // 6) log-softmax
    row_lse_kernel<<<MM, 256>>>(out);
    sub_lse_kernel<<<MM, 256>>>(out);

    // 7) optional hidden-state tail
    if (out_size >= MM * VOC + 2 * BB * HID)
        write_hidden_kernel<<<(2 * BB * HID + 255) / 256, 256>>>(out);
}

// round 7
// speedup vs baseline: 1.7148x; 1.7148x over previous
#include <cuda_runtime.h>
#include <cuda_bf16.h>
#include <math.h>
#include <stdint.h>

#define HID   1024
#define GATES 4096
#define BB    8
#define TT    256
#define MM    2048
#define VOC   50257

typedef unsigned long long u64;

// ---------------- scratch ----------------
__device__ float g_emb[(size_t)MM * HID];
__device__ float g_xproj[(size_t)MM * GATES];
__device__ float g_hall[(size_t)MM * HID];
__device__ float g_hbuf[2][BB * HID];
__device__ float g_c[BB * HID];
__device__ float g_lse[MM];
__device__ int   g_bar_cnt = 0;
__device__ int   g_bar_gen = 0;

// bf16 split operands
__device__ __nv_bfloat16 g_ebh[(size_t)VOC * HID];
__device__ __nv_bfloat16 g_ebl[(size_t)VOC * HID];
__device__ __nv_bfloat16 g_wh [(size_t)GATES * HID];
__device__ __nv_bfloat16 g_wl [(size_t)GATES * HID];
__device__ __nv_bfloat16 g_xh [(size_t)MM * HID];
__device__ __nv_bfloat16 g_xl [(size_t)MM * HID];
__device__ __nv_bfloat16 g_hh2[(size_t)MM * HID];
__device__ __nv_bfloat16 g_hl2[(size_t)MM * HID];

// ---------------- helpers ----------------
__device__ __forceinline__ void cpasync16(uint32_t dst, const void* src) {
    asm volatile("cp.async.cg.shared.global [%0], [%1], 16;\n" :: "r"(dst), "l"(src));
}
#define CP_COMMIT() asm volatile("cp.async.commit_group;\n")

__device__ __forceinline__ u64 fma2(u64 a, u64 b, u64 c) {
    u64 d; asm("fma.rn.f32x2 %0, %1, %2, %3;" : "=l"(d) : "l"(a), "l"(b), "l"(c));
    return d;
}
__device__ __forceinline__ float2 upk2(u64 v) {
    float2 r; asm("mov.b64 {%0, %1}, %2;" : "=f"(r.x), "=f"(r.y) : "l"(v)); return r;
}
__device__ __forceinline__ float fexp(float x) {
    float y = fmaxf(x * 1.4426950408889634f, -120.f);
    float n = rintf(y);
    float f = y - n;
    float p = 0.0013333558f;
    p = fmaf(p, f, 0.0096181291f);
    p = fmaf(p, f, 0.0555041087f);
    p = fmaf(p, f, 0.2402265069f);
    p = fmaf(p, f, 0.6931471806f);
    p = fmaf(p, f, 1.0f);
    return p * __int_as_float(((int)n + 127) << 23);
}

__device__ __forceinline__ void mma16816(float* d, const uint32_t* a, const uint32_t* b) {
    asm volatile(
        "mma.sync.aligned.m16n8k16.row.col.f32.bf16.bf16.f32 "
        "{%0,%1,%2,%3}, {%4,%5,%6,%7}, {%8,%9}, {%0,%1,%2,%3};"
        : "+f"(d[0]), "+f"(d[1]), "+f"(d[2]), "+f"(d[3])
        : "r"(a[0]), "r"(a[1]), "r"(a[2]), "r"(a[3]), "r"(b[0]), "r"(b[1]));
}

// ---------------- small kernels ----------------
__global__ void zero_state_kernel() {
    int i = blockIdx.x * blockDim.x + threadIdx.x;
    if (i < BB * HID) { g_hbuf[0][i] = 0.f; g_c[i] = 0.f; }
}

__global__ void gather_kernel(const int* __restrict__ x, const float* __restrict__ embW) {
    int m = blockIdx.x;
    int t = m >> 3, b = m & 7;
    int tok = x[b * TT + t];
    const float4* src = (const float4*)(embW + (size_t)tok * HID);
    float4* dst = (float4*)(g_emb + (size_t)m * HID);
    dst[threadIdx.x] = src[threadIdx.x];
}

__global__ void split_kernel(const float* __restrict__ s, __nv_bfloat16* __restrict__ h,
                             __nv_bfloat16* __restrict__ l, long n) {
    long i = blockIdx.x * (long)blockDim.x + threadIdx.x;
    long st = (long)gridDim.x * blockDim.x;
    for (; i < n; i += st) {
        float f = s[i];
        __nv_bfloat16 hv = __float2bfloat16(f);
        h[i] = hv;
        l[i] = __float2bfloat16(f - __bfloat162float(hv));
    }
}

// ---------------- mma.sync split-bf16 NT GEMM ----------------
// C[m][n] = sum_k A[m][k]*B[n][k] + bias1[n] + bias2[n]
// 3 terms: Ahi*Bhi + Ahi*Blo + Alo*Bhi, fp32 accum.
// CTA tile 128x128x32, 8 warps (2x4), warp tile 64x32. 2-stage cp.async.
#define BKP 40                         // padded bf16 row stride
#define BUF_B (128 * BKP * 2)          // 10240 bytes per operand buffer
#define STAGE_B (4 * BUF_B)            // 40960
#define MMSMEM (2 * STAGE_B)           // 81920

__device__ __forceinline__ void stage_chunk_mma(
    char* smem, int stage, int tid, int kc,
    const __nv_bfloat16* Ah, const __nv_bfloat16* Al,
    const __nv_bfloat16* Bh, const __nv_bfloat16* Bl,
    int m0, int n0, int Nrows, int K)
{
    uint32_t sb = (uint32_t)__cvta_generic_to_shared(smem) + (uint32_t)stage * STAGE_B;
    #pragma unroll
    for (int i = 0; i < 8; i++) {
        int u = tid + 256 * i;              // 0..2047
        int buf = u >> 9;                   // 0:Ah 1:Al 2:Bh 3:Bl
        int o = u & 511;
        int row = o >> 2;
        int col = (o & 3) * 8;
        const __nv_bfloat16* src;
        if (buf < 2) {
            src = ((buf == 0) ? Ah : Al) + (size_t)(m0 + row) * K + kc + col;
        } else {
            int n = n0 + row; if (n >= Nrows) n = Nrows - 1;
            src = ((buf == 2) ? Bh : Bl) + (size_t)n * K + kc + col;
        }
        cpasync16(sb + (uint32_t)(buf * BUF_B + (row * BKP + col) * 2), src);
    }
}

__global__ void __launch_bounds__(256)
mm_bf16_kernel(const __nv_bfloat16* __restrict__ Ah, const __nv_bfloat16* __restrict__ Al,
               const __nv_bfloat16* __restrict__ Bh, const __nv_bfloat16* __restrict__ Bl,
               const float* __restrict__ bias1, const float* __restrict__ bias2,
               float* __restrict__ C, int Nrows, int ldc, int K)
{
    extern __shared__ char smem[];
    int tid = threadIdx.x;
    int wid = tid >> 5, lane = tid & 31;
    int m0 = blockIdx.x * 128;             // x = m-block (B-tile shared across concurrent CTAs)
    int n0 = blockIdx.y * 128;
    int m0w = (wid >> 2) * 64;             // warp tile origin in CTA
    int n0w = (wid & 3) * 32;
    const int NC = K / 32;

    float acc[4][4][4];
    #pragma unroll
    for (int mf = 0; mf < 4; mf++)
        #pragma unroll
        for (int nf = 0; nf < 4; nf++)
            #pragma unroll
            for (int e = 0; e < 4; e++) acc[mf][nf][e] = 0.f;

    stage_chunk_mma(smem, 0, tid, 0, Ah, Al, Bh, Bl, m0, n0, Nrows, K);
    CP_COMMIT();
    stage_chunk_mma(smem, 1, tid, 32, Ah, Al, Bh, Bl, m0, n0, Nrows, K);
    CP_COMMIT();

    int ar = lane >> 2;                    // 0..7
    int ac = (lane & 3) * 2;               // 0,2,4,6

    for (int c = 0; c < NC; c++) {
        if (c < NC - 1) asm volatile("cp.async.wait_group 1;" ::: "memory");
        else            asm volatile("cp.async.wait_group 0;" ::: "memory");
        __syncthreads();

        const __nv_bfloat16* st = (const __nv_bfloat16*)(smem + (c & 1) * STAGE_B);
        const __nv_bfloat16* pAh = st;
        const __nv_bfloat16* pAl = st + 128 * BKP;
        const __nv_bfloat16* pBh = st + 2 * 128 * BKP;
        const __nv_bfloat16* pBl = st + 3 * 128 * BKP;

        #pragma unroll
        for (int ks = 0; ks < 32; ks += 16) {
            uint32_t fAh[4][4], fAl[4][4], fBh[4][2], fBl[4][2];
            #pragma unroll
            for (int mf = 0; mf < 4; mf++) {
                int r = m0w + mf * 16 + ar;
                int cc = ks + ac;
                fAh[mf][0] = *(const uint32_t*)(pAh + r * BKP + cc);
                fAh[mf][1] = *(const uint32_t*)(pAh + (r + 8) * BKP + cc);
                fAh[mf][2] = *(const uint32_t*)(pAh + r * BKP + cc + 8);
                fAh[mf][3] = *(const uint32_t*)(pAh + (r + 8) * BKP + cc + 8);
                fAl[mf][0] = *(const uint32_t*)(pAl + r * BKP + cc);
                fAl[mf][1] = *(const uint32_t*)(pAl + (r + 8) * BKP + cc);
                fAl[mf][2] = *(const uint32_t*)(pAl + r * BKP + cc + 8);
                fAl[mf][3] = *(const uint32_t*)(pAl + (r + 8) * BKP + cc + 8);
            }
            #pragma unroll
            for (int nf = 0; nf < 4; nf++) {
                int n = n0w + nf * 8 + ar;
                int kk = ks + ac;
                fBh[nf][0] = *(const uint32_t*)(pBh + n * BKP + kk);
                fBh[nf][1] = *(const uint32_t*)(pBh + n * BKP + kk + 8);
                fBl[nf][0] = *(const uint32_t*)(pBl + n * BKP + kk);
                fBl[nf][1] = *(const uint32_t*)(pBl + n * BKP + kk + 8);
            }
            #pragma unroll
            for (int mf = 0; mf < 4; mf++)
                #pragma unroll
                for (int nf = 0; nf < 4; nf++) {
                    mma16816(acc[mf][nf], fAh[mf], fBh[nf]);
                    mma16816(acc[mf][nf], fAh[mf], fBl[nf]);
                    mma16816(acc[mf][nf], fAl[mf], fBh[nf]);
                }
        }
        __syncthreads();
        if (c + 2 < NC) {
            stage_chunk_mma(smem, c & 1, tid, (c + 2) * 32, Ah, Al, Bh, Bl, m0, n0, Nrows, K);
            CP_COMMIT();
        }
    }

    // epilogue: SCALAR global stores (ldc may be odd -> no float2), bias added
    #pragma unroll
    for (int mf = 0; mf < 4; mf++) {
        int row0 = m0 + m0w + mf * 16 + ar;
        float* r0p = C + (size_t)row0 * ldc;
        float* r1p = C + (size_t)(row0 + 8) * ldc;
        #pragma unroll
        for (int nf = 0; nf < 4; nf++) {
            int col = n0 + n0w + nf * 8 + ac;
            #pragma unroll
            for (int e = 0; e < 2; e++) {
                int cc = col + e;
                if (cc < Nrows) {
                    float bv = 0.f;
                    if (bias1) bv += bias1[cc];
                    if (bias2) bv += bias2[cc];
                    r0p[cc] = acc[mf][nf][e] + bv;
                    r1p[cc] = acc[mf][nf][2 + e] + bv;
                }
            }
        }
    }
}

// ---------------- persistent LSTM ----------------
#define LS_SMEM_FLOATS (32*1024 + 8*1024 + 256*65 + 256)

__global__ void __launch_bounds__(256)
lstm_persistent_kernel(const float* __restrict__ w_hh)
{
    extern __shared__ float sm[];
    float* sm_w     = sm;
    float* sm_h     = sm + 32 * 1024;
    float* sm_part  = sm_h + 8 * 1024;
    float* sm_gates = sm_part + 256 * 65;

    int tid = threadIdx.x;
    int jb = blockIdx.x * 8;

    {
        uint32_t sw = (uint32_t)__cvta_generic_to_shared(sm_w);
        #pragma unroll
        for (int i = 0; i < 32; i++) {
            int m = tid + 256 * i;
            int row = m >> 8;
            int c = m & 255;
            int g = row >> 3, jl = row & 7;
            const float4* src = (const float4*)w_hh + (size_t)(g * HID + jb + jl) * 256 + c;
            cpasync16(sw + (uint32_t)m * 16, src);
        }
        CP_COMMIT();
        asm volatile("cp.async.wait_group 0;\n" ::: "memory");
        __syncthreads();
    }

    int wid = tid >> 5, lane = tid & 31;
    int rg = wid & 3;
    int ks = (wid >> 2) * 32 + lane;

    int ejl = tid >> 3, eb = tid & 7;
    float c_reg = 0.f;

    for (int t = 0; t < TT; t++) {
        const float* hprev = g_hbuf[t & 1];
        float* hnext = g_hbuf[(t + 1) & 1];

        {
            const float4* hp4 = (const float4*)hprev;
            float4* hs4 = (float4*)sm_h;
            #pragma unroll
            for (int i = 0; i < 8; i++) {
                int f = tid + 256 * i;
                hs4[f] = __ldcg(hp4 + f);
            }
        }
        __syncthreads();

        u64 acc[8][8];
        #pragma unroll
        for (int r = 0; r < 8; r++)
            #pragma unroll
            for (int b = 0; b < 8; b++) acc[r][b] = 0ull;

        const ulonglong2* w2 = (const ulonglong2*)sm_w;
        const ulonglong2* h2 = (const ulonglong2*)sm_h;
        #pragma unroll
        for (int q = 0; q < 4; q++) {
            int kb = q * 64 + ks;
            ulonglong2 hv[8];
            #pragma unroll
            for (int b = 0; b < 8; b++) hv[b] = h2[b * 256 + kb];
            #pragma unroll
            for (int r = 0; r < 8; r++) {
                ulonglong2 wv = w2[(rg * 8 + r) * 256 + kb];
                #pragma unroll
                for (int b = 0; b < 8; b++) {
                    acc[r][b] = fma2(wv.x, hv[b].x, acc[r][b]);
                    acc[r][b] = fma2(wv.y, hv[b].y, acc[r][b]);
                }
            }
        }

        #pragma unroll
        for (int r = 0; r < 8; r++)
            #pragma unroll
            for (int b = 0; b < 8; b++) {
                float2 v = upk2(acc[r][b]);
                sm_part[((rg * 8 + r) * 8 + b) * 65 + ks] = v.x + v.y;
            }
        __syncthreads();

        {
            float s0 = 0.f, s1 = 0.f, s2 = 0.f, s3 = 0.f;
            const float* p = sm_part + tid * 65;
            #pragma unroll
            for (int i = 0; i < 64; i += 4) {
                s0 += p[i]; s1 += p[i + 1]; s2 += p[i + 2]; s3 += p[i + 3];
            }
            int row = tid >> 3, b = tid & 7;
            int g = row >> 3, jl = row & 7;
            sm_gates[tid] = (s0 + s1) + (s2 + s3)
                          + g_xproj[((size_t)t * BB + b) * GATES + g * HID + jb + jl];
        }
        __syncthreads();

        if (tid < 64) {
            int j = jb + ejl;
            float gi = sm_gates[(0 * 8 + ejl) * 8 + eb];
            float gf = sm_gates[(1 * 8 + ejl) * 8 + eb];
            float gg = sm_gates[(2 * 8 + ejl) * 8 + eb];
            float go = sm_gates[(3 * 8 + ejl) * 8 + eb];
            gi = 1.f / (1.f + expf(-gi));
            gf = 1.f / (1.f + expf(-gf));
            gg = tanhf(gg);
            go = 1.f / (1.f + expf(-go));
            c_reg = gf * c_reg + gi * gg;
            float h = go * tanhf(c_reg);
            hnext[eb * HID + j] = h;
            g_hall[((size_t)eb * TT + t) * HID + j] = h;
            if (t == TT - 1) g_c[eb * HID + j] = c_reg;
            __threadfence();
        }

        __syncthreads();
        if (tid == 0) {
            int gen = *((volatile int*)&g_bar_gen);
            __threadfence();
            if (atomicAdd(&g_bar_cnt, 1) == (int)gridDim.x - 1) {
                g_bar_cnt = 0;
                __threadfence();
                atomicAdd(&g_bar_gen, 1);
            } else {
                while (*((volatile int*)&g_bar_gen) == gen) { }
            }
            __threadfence();
        }
        __syncthreads();
    }
}

// ---------------- log-softmax ----------------
__global__ void __launch_bounds__(256)
row_lse_kernel(const float* __restrict__ logits)
{
    int row = blockIdx.x;
    const float* p = logits + (size_t)row * VOC;
    float m = -1e30f, s = 0.f;
    for (int i = threadIdx.x; i < VOC; i += 256) {
        float v = p[i];
        if (v > m) { s = s * fexp(m - v) + 1.f; m = v; }
        else       { s += fexp(v - m); }
    }
    __shared__ float sm[256], ss[256];
    sm[threadIdx.x] = m; ss[threadIdx.x] = s;
    __syncthreads();
    for (int off = 128; off; off >>= 1) {
        if (threadIdx.x < off) {
            float m1 = sm[threadIdx.x], s1 = ss[threadIdx.x];
            float m2 = sm[threadIdx.x + off], s2 = ss[threadIdx.x + off];
            float mm = fmaxf(m1, m2);
            sm[threadIdx.x] = mm;
            ss[threadIdx.x] = s1 * fexp(m1 - mm) + s2 * fexp(m2 - mm);
        }
        __syncthreads();
    }
    if (threadIdx.x == 0) g_lse[row] = sm[0] + logf(ss[0]);
}

__global__ void __launch_bounds__(256)
sub_lse_kernel(float* __restrict__ out)
{
    int row = blockIdx.x;
    float l = g_lse[row];
    float* p = out + (size_t)row * VOC;
    for (int i = threadIdx.x; i < VOC; i += 256) p[i] -= l;
}

__global__ void write_hidden_kernel(float* __restrict__ out)
{
    int i = blockIdx.x * blockDim.x + threadIdx.x;
    size_t base = (size_t)MM * VOC;
    if (i < BB * HID)               out[base + i] = g_hbuf[0][i];
    else if (i < 2 * BB * HID)      out[base + i] = g_c[i - BB * HID];
}

// ---------------- launcher ----------------
extern "C" void kernel_launch(void* const* d_in, const int* in_sizes, int n_in,
                              void* d_out, int out_size)
{
    const int*   x     = (const int*)  d_in[0];
    const float* emb_W = (const float*)d_in[1];
    const float* w_ih  = (const float*)d_in[2];
    const float* w_hh  = (const float*)d_in[3];
    const float* b_ih  = (const float*)d_in[4];
    const float* b_hh  = (const float*)d_in[5];
    const float* dec_b = (const float*)d_in[6];
    float* out = (float*)d_out;

    float* emb_p;   cudaGetSymbolAddress((void**)&emb_p,   g_emb);
    float* xproj_p; cudaGetSymbolAddress((void**)&xproj_p, g_xproj);
    float* hall_p;  cudaGetSymbolAddress((void**)&hall_p,  g_hall);
    __nv_bfloat16 *ebh, *ebl, *wh, *wl, *xh, *xl, *hh2, *hl2;
    cudaGetSymbolAddress((void**)&ebh, g_ebh);
    cudaGetSymbolAddress((void**)&ebl, g_ebl);
    cudaGetSymbolAddress((void**)&wh,  g_wh);
    cudaGetSymbolAddress((void**)&wl,  g_wl);
    cudaGetSymbolAddress((void**)&xh,  g_xh);
    cudaGetSymbolAddress((void**)&xl,  g_xl);
    cudaGetSymbolAddress((void**)&hh2, g_hh2);
    cudaGetSymbolAddress((void**)&hl2, g_hl2);

    const int ls_smem = LS_SMEM_FLOATS * 4;
    cudaFuncSetAttribute(lstm_persistent_kernel,
                         cudaFuncAttributeMaxDynamicSharedMemorySize, ls_smem);
    cudaFuncSetAttribute(mm_bf16_kernel,
                         cudaFuncAttributeMaxDynamicSharedMemorySize, MMSMEM);

    zero_state_kernel<<<(BB * HID + 255) / 256, 256>>>();
    gather_kernel<<<MM, 256>>>(x, emb_W);

    split_kernel<<<4096, 256>>>(emb_W, ebh, ebl, (long)VOC * HID);
    split_kernel<<<1024, 256>>>(w_ih,  wh,  wl,  (long)GATES * HID);
    split_kernel<<<512,  256>>>(emb_p, xh,  xl,  (long)MM * HID);

    // x_proj = emb @ w_ih^T + (b_ih + b_hh)
    {
        dim3 grid(MM / 128, GATES / 128);          // x = m-blocks, y = n-blocks
        mm_bf16_kernel<<<grid, 256, MMSMEM>>>(xh, xl, wh, wl, b_ih, b_hh,
                                              xproj_p, GATES, GATES, HID);
    }

    lstm_persistent_kernel<<<HID / 8, 256, ls_smem>>>(w_hh);

    split_kernel<<<512, 256>>>(hall_p, hh2, hl2, (long)MM * HID);

    // decoder: logits = h_all @ emb_W^T + dec_b
    {
        dim3 grid(MM / 128, (VOC + 127) / 128);    // 16 x 393
        mm_bf16_kernel<<<grid, 256, MMSMEM>>>(hh2, hl2, ebh, ebl, dec_b,
                                              (const float*)0, out, VOC, VOC, HID);
    }

    row_lse_kernel<<<MM, 256>>>(out);
    sub_lse_kernel<<<MM, 256>>>(out);

    if (out_size >= MM * VOC + 2 * BB * HID)
        write_hidden_kernel<<<(2 * BB * HID + 255) / 256, 256>>>(out);
}